// round 5
// baseline (speedup 1.0000x reference)
#include <cuda_runtime.h>
#include <cstdint>

// Problem constants (fixed by the reference)
#define B_SZ   16384
#define S_GRID 7
#define CELLS_PER_B   49            // 7*7
#define CH     30
#define N_CELLS (B_SZ * CELLS_PER_B)   // 802816
#define BLOCK  256
#define GRID_N (N_CELLS / BLOCK)       // 3136 exactly

#define PREF_F 12                   // staged prefix floats per cell (t[0..11], 48 B)
#define PREF_CHUNKS 6               // 6 x 8-byte cp.async chunks per cell

#define CELL_PX 64.0f
#define IMG_PX  448.0f

// grid-wide accumulator (zero-initialized at module load; reset by the last
// finishing block -> deterministic across graph replays, no zeroing kernel)
__device__ float        g_acc;
__device__ unsigned int g_done;

__device__ __forceinline__ uint32_t smem_u32(const void* p) {
    uint32_t a;
    asm("{ .reg .u64 t; cvta.to.shared.u64 t, %1; cvt.u32.u64 %0, t; }"
        : "=r"(a) : "l"(p));
    return a;
}

__device__ __forceinline__ float4 decode_box(float p0, float p1, float p2, float p3,
                                             float gx, float gy) {
    float cx = p0 * CELL_PX + gx;
    float cy = p1 * CELL_PX + gy;
    float w  = p2 * IMG_PX;
    float h  = p3 * IMG_PX;
    float4 r;
    r.x = fminf(fmaxf(cx - w * 0.5f, 0.0f), IMG_PX);
    r.y = fminf(fmaxf(cy - h * 0.5f, 0.0f), IMG_PX);
    r.z = fminf(fmaxf(cx + w * 0.5f, 0.0f), IMG_PX);
    r.w = fminf(fmaxf(cy + h * 0.5f, 0.0f), IMG_PX);
    return r;
}

__device__ __forceinline__ float iou_fn(float4 a, float4 b) {
    float l  = fmaxf(a.x, b.x);
    float r  = fminf(a.z, b.z);
    float tt = fmaxf(a.y, b.y);
    float bo = fminf(a.w, b.w);
    bool m = (l < r) && (tt < bo);
    float inter = (r - l) * (bo - tt);
    float uni = (a.z - a.x) * (a.w - a.y) + (b.z - b.x) * (b.w - b.y);
    return m ? inter / (uni - inter) : 0.0f;
}

__global__ __launch_bounds__(BLOCK) void yolo_loss_kernel(
    const float* __restrict__ inp,   // [B, 30, 7, 7]
    const float* __restrict__ tgt,   // [B, 7, 7, 30]  == [N_CELLS, 30]
    float* __restrict__ out)
{
    __shared__ float st[BLOCK * PREF_F];   // 256 cells x 12 floats = 12288 B
    __shared__ float warp_sums[BLOCK / 32];

    const int n0 = blockIdx.x * BLOCK;

    // ---- stage per-cell 48-B target prefixes via 8-B cp.async chunks ----
    // chunk g (0..1535): cell = g/6, k = g%6 -> gmem byte addr (n0+cell)*120 + k*8
    // smem byte addr g*8  => smem layout: st[cell*12 + 2k .. +2k+1]
    {
        const char* tb = reinterpret_cast<const char*>(tgt) + (size_t)n0 * (CH * 4);
        uint32_t st_base = smem_u32(st);
        #pragma unroll
        for (int it = 0; it < PREF_CHUNKS; it++) {
            int g = threadIdx.x + it * BLOCK;
            int cell = g / PREF_CHUNKS;
            int k    = g - cell * PREF_CHUNKS;
            const char* src = tb + cell * (CH * 4) + k * 8;
            asm volatile("cp.async.ca.shared.global [%0], [%1], 8;\n"
                         :: "r"(st_base + g * 8), "l"(src));
        }
        asm volatile("cp.async.commit_group;\n" ::: "memory");
    }

    // ---- issue all 30 input loads while cp.async is in flight ----
    const int n    = n0 + threadIdx.x;
    const int b    = n / CELLS_PER_B;
    const int cell = n - b * CELLS_PER_B;
    const int row  = cell / S_GRID;
    const int col  = cell - row * S_GRID;
    const float gx = (float)col * CELL_PX;
    const float gy = (float)row * CELL_PX;

    // input: channel-major, stride 49 per channel; contiguous across threads
    const float* xb = inp + (size_t)b * (CH * CELLS_PER_B) + cell;
    float x[CH];
    #pragma unroll
    for (int c = 0; c < CH; c++)
        x[c] = __ldg(&xb[c * CELLS_PER_B]);

    asm volatile("cp.async.wait_group 0;\n" ::: "memory");
    __syncthreads();

    const float* t = st + threadIdx.x * PREF_F;

    float4 pb1 = decode_box(x[0], x[1], x[2], x[3], gx, gy);
    float4 pb2 = decode_box(x[5], x[6], x[7], x[8], gx, gy);
    float4 tb1 = decode_box(t[0], t[1], t[2], t[3], gx, gy);
    float4 tb2 = decode_box(t[5], t[6], t[7], t[8], gx, gy);

    float iou1 = iou_fn(pb1, tb1);
    float iou2 = iou_fn(pb2, tb2);
    bool  mask = iou1 < iou2;
    float iou  = mask ? iou2 : iou1;

    float s0 = mask ? x[5] : x[0];
    float s1 = mask ? x[6] : x[1];
    float s2 = mask ? x[7] : x[2];
    float s3 = mask ? x[8] : x[3];
    float s4 = mask ? x[9] : x[4];

    float w = (t[4] == 1.0f) ? 1.0f : 0.0f;

    float d0 = s0 - t[0], d1 = s1 - t[1];
    float coord = d0 * d0 + d1 * d1;
    float e2 = sqrtf(s2) - sqrtf(t[2]);
    float e3 = sqrtf(s3) - sqrtf(t[3]);
    float size = e2 * e2 + e3 * e3;
    float dc = s4 - iou;
    float conf = dc * dc;
    float noobj = s4 * s4;

    // class term: only cells with an object contribute, and only they read
    // the target class channels (75% of that traffic skipped at sector level)
    float cls = 0.0f;
    if (w != 0.0f) {
        const float* trow = tgt + (size_t)n * CH + 10;
        #pragma unroll 5
        for (int c = 0; c < 20; c++) {
            float d = x[10 + c] - __ldg(&trow[c]);
            cls += d * d;
        }
    }

    float loss = w * (5.0f * coord + 5.0f * size + conf + cls)
               + (1.0f - w) * 0.5f * noobj;

    // ---- block reduction ----
    #pragma unroll
    for (int o = 16; o > 0; o >>= 1)
        loss += __shfl_down_sync(0xFFFFFFFFu, loss, o);

    const int lane = threadIdx.x & 31;
    const int wid  = threadIdx.x >> 5;
    if (lane == 0) warp_sums[wid] = loss;
    __syncthreads();

    if (threadIdx.x == 0) {
        float v = 0.0f;
        #pragma unroll
        for (int i = 0; i < BLOCK / 32; i++) v += warp_sums[i];

        atomicAdd(&g_acc, v);
        __threadfence();
        unsigned int done = atomicAdd(&g_done, 1u);
        if (done == GRID_N - 1) {
            out[0] = g_acc;      // publish result
            g_acc  = 0.0f;       // reset for next graph replay
            g_done = 0u;
        }
    }
}

extern "C" void kernel_launch(void* const* d_in, const int* in_sizes, int n_in,
                              void* d_out, int out_size) {
    const float* inp = (const float*)d_in[0];   // [16384, 30, 7, 7]
    const float* tgt = (const float*)d_in[1];   // [16384, 7, 7, 30]
    float* out = (float*)d_out;                 // scalar

    yolo_loss_kernel<<<GRID_N, BLOCK>>>(inp, tgt, out);
}

// round 6
// speedup vs baseline: 1.2282x; 1.2282x over previous
#include <cuda_runtime.h>
#include <cstdint>

// Problem constants (fixed by the reference)
#define B_SZ   16384
#define S_GRID 7
#define CELLS_PER_B   49             // 7*7
#define CH     30
#define FLOATS_PER_B (CELLS_PER_B * CH)   // 1470 floats = 5880 B per batch
#define BPB    4                     // batches per block
#define CELLS  (BPB * CELLS_PER_B)   // 196 active cells
#define BLOCK  256
#define GRID_N (B_SZ / BPB)          // 4096 blocks
#define SLAB_BYTES (BPB * FLOATS_PER_B * 4)   // 23520 B per tensor slab

#define CELL_PX 64.0f
#define IMG_PX  448.0f

// grid-wide accumulator (zero-initialized at module load; reset by the last
// finishing block -> deterministic across graph replays)
__device__ float        g_acc;
__device__ unsigned int g_done;

__device__ __forceinline__ uint32_t smem_u32(const void* p) {
    uint32_t a;
    asm("{ .reg .u64 t; cvta.to.shared.u64 t, %1; cvt.u32.u64 %0, t; }"
        : "=r"(a) : "l"(p));
    return a;
}

__device__ __forceinline__ float4 decode_box(float p0, float p1, float p2, float p3,
                                             float gx, float gy) {
    float cx = p0 * CELL_PX + gx;
    float cy = p1 * CELL_PX + gy;
    float w  = p2 * IMG_PX;
    float h  = p3 * IMG_PX;
    float4 r;
    r.x = fminf(fmaxf(cx - w * 0.5f, 0.0f), IMG_PX);
    r.y = fminf(fmaxf(cy - h * 0.5f, 0.0f), IMG_PX);
    r.z = fminf(fmaxf(cx + w * 0.5f, 0.0f), IMG_PX);
    r.w = fminf(fmaxf(cy + h * 0.5f, 0.0f), IMG_PX);
    return r;
}

__device__ __forceinline__ float iou_fn(float4 a, float4 b) {
    float l  = fmaxf(a.x, b.x);
    float r  = fminf(a.z, b.z);
    float tt = fmaxf(a.y, b.y);
    float bo = fminf(a.w, b.w);
    bool m = (l < r) && (tt < bo);
    float inter = (r - l) * (bo - tt);
    float uni = (a.z - a.x) * (a.w - a.y) + (b.z - b.x) * (b.w - b.y);
    return m ? inter / (uni - inter) : 0.0f;
}

__global__ __launch_bounds__(BLOCK) void yolo_loss_kernel(
    const float* __restrict__ inp,   // [B, 30, 7, 7]  (batch slab contiguous)
    const float* __restrict__ tgt,   // [B, 7, 7, 30]  (batch slab contiguous)
    float* __restrict__ out)
{
    __shared__ alignas(16) float in_s[BPB * FLOATS_PER_B];  // 23520 B
    __shared__ alignas(16) float tg_s[BPB * FLOATS_PER_B];  // 23520 B
    __shared__ alignas(8)  uint64_t mbar;
    __shared__ float warp_sums[BLOCK / 32];

    const int tid = threadIdx.x;
    const uint32_t mbar_a = smem_u32(&mbar);

    if (tid == 0) {
        asm volatile("mbarrier.init.shared.b64 [%0], 1;" :: "r"(mbar_a) : "memory");
    }
    __syncthreads();

    if (tid == 0) {
        asm volatile("mbarrier.arrive.expect_tx.shared.b64 _, [%0], %1;"
                     :: "r"(mbar_a), "r"(2 * SLAB_BYTES) : "memory");
        const char* in_src = reinterpret_cast<const char*>(inp) + (size_t)blockIdx.x * SLAB_BYTES;
        const char* tg_src = reinterpret_cast<const char*>(tgt) + (size_t)blockIdx.x * SLAB_BYTES;
        asm volatile("cp.async.bulk.shared::cluster.global.mbarrier::complete_tx::bytes "
                     "[%0], [%1], %2, [%3];"
                     :: "r"(smem_u32(in_s)), "l"(in_src), "r"(SLAB_BYTES), "r"(mbar_a)
                     : "memory");
        asm volatile("cp.async.bulk.shared::cluster.global.mbarrier::complete_tx::bytes "
                     "[%0], [%1], %2, [%3];"
                     :: "r"(smem_u32(tg_s)), "l"(tg_src), "r"(SLAB_BYTES), "r"(mbar_a)
                     : "memory");
    }

    // wait for both bulk copies (phase 0; barrier is freshly initialized each launch)
    {
        uint32_t done;
        asm volatile(
            "{\n\t.reg .pred p;\n\t"
            "mbarrier.try_wait.parity.acquire.cta.shared::cta.b64 p, [%1], 0;\n\t"
            "selp.b32 %0, 1, 0, p;\n\t}"
            : "=r"(done) : "r"(mbar_a) : "memory");
        if (!done) {
            asm volatile(
                "{\n\t.reg .pred P1;\n\t"
                "WL_%=:\n\t"
                "mbarrier.try_wait.parity.acquire.cta.shared::cta.b64 P1, [%0], 0, 0x989680;\n\t"
                "@P1 bra.uni WD_%=;\n\t"
                "bra.uni WL_%=;\n\t"
                "WD_%=:\n\t}"
                :: "r"(mbar_a) : "memory");
        }
    }

    float loss = 0.0f;
    if (tid < CELLS) {
        const int b_loc = tid / CELLS_PER_B;
        const int cell  = tid - b_loc * CELLS_PER_B;
        const int row   = cell / S_GRID;
        const int col   = cell - row * S_GRID;
        const float gx  = (float)col * CELL_PX;
        const float gy  = (float)row * CELL_PX;

        // input: channel-major within batch slab; stride-1 across threads per channel
        const float* xs = in_s + b_loc * FLOATS_PER_B + cell;
        const float* t  = tg_s + tid * CH;

        float x0 = xs[0 * CELLS_PER_B], x1 = xs[1 * CELLS_PER_B];
        float x2 = xs[2 * CELLS_PER_B], x3 = xs[3 * CELLS_PER_B];
        float x4 = xs[4 * CELLS_PER_B], x5 = xs[5 * CELLS_PER_B];
        float x6 = xs[6 * CELLS_PER_B], x7 = xs[7 * CELLS_PER_B];
        float x8 = xs[8 * CELLS_PER_B], x9 = xs[9 * CELLS_PER_B];

        float4 pb1 = decode_box(x0, x1, x2, x3, gx, gy);
        float4 pb2 = decode_box(x5, x6, x7, x8, gx, gy);
        float4 tb1 = decode_box(t[0], t[1], t[2], t[3], gx, gy);
        float4 tb2 = decode_box(t[5], t[6], t[7], t[8], gx, gy);

        float iou1 = iou_fn(pb1, tb1);
        float iou2 = iou_fn(pb2, tb2);
        bool  mask = iou1 < iou2;
        float iou  = mask ? iou2 : iou1;

        float s0 = mask ? x5 : x0;
        float s1 = mask ? x6 : x1;
        float s2 = mask ? x7 : x2;
        float s3 = mask ? x8 : x3;
        float s4 = mask ? x9 : x4;

        float w = (t[4] == 1.0f) ? 1.0f : 0.0f;

        float d0 = s0 - t[0], d1 = s1 - t[1];
        float coord = d0 * d0 + d1 * d1;
        float e2 = sqrtf(s2) - sqrtf(t[2]);
        float e3 = sqrtf(s3) - sqrtf(t[3]);
        float size = e2 * e2 + e3 * e3;
        float dc = s4 - iou;
        float conf = dc * dc;
        float noobj = s4 * s4;

        float cls = 0.0f;
        #pragma unroll
        for (int c = 10; c < CH; c++) {
            float d = xs[c * CELLS_PER_B] - t[c];
            cls += d * d;
        }

        loss = w * (5.0f * coord + 5.0f * size + conf + cls)
             + (1.0f - w) * 0.5f * noobj;
    }

    // ---- block reduction ----
    #pragma unroll
    for (int o = 16; o > 0; o >>= 1)
        loss += __shfl_down_sync(0xFFFFFFFFu, loss, o);

    const int lane = tid & 31;
    const int wid  = tid >> 5;
    if (lane == 0) warp_sums[wid] = loss;
    __syncthreads();

    if (tid == 0) {
        float v = 0.0f;
        #pragma unroll
        for (int i = 0; i < BLOCK / 32; i++) v += warp_sums[i];

        atomicAdd(&g_acc, v);
        __threadfence();
        unsigned int done = atomicAdd(&g_done, 1u);
        if (done == GRID_N - 1) {
            out[0] = g_acc;      // publish result
            g_acc  = 0.0f;       // reset for next graph replay
            g_done = 0u;
        }
    }
}

extern "C" void kernel_launch(void* const* d_in, const int* in_sizes, int n_in,
                              void* d_out, int out_size) {
    const float* inp = (const float*)d_in[0];   // [16384, 30, 7, 7]
    const float* tgt = (const float*)d_in[1];   // [16384, 7, 7, 30]
    float* out = (float*)d_out;                 // scalar

    yolo_loss_kernel<<<GRID_N, BLOCK>>>(inp, tgt, out);
}

// round 8
// speedup vs baseline: 1.2975x; 1.0564x over previous
#include <cuda_runtime.h>
#include <cstdint>

// Problem constants (fixed by the reference)
#define B_SZ   16384
#define S_GRID 7
#define CELLS_PER_B   49            // 7*7
#define CH     30
#define N_CELLS (B_SZ * CELLS_PER_B)   // 802816
#define BLOCK  256
#define GRID_N (N_CELLS / BLOCK)       // 3136 exactly
#define SLAB_BYTES (BLOCK * CH * 4)    // 30720 B contiguous target slab per tile

#define CELL_PX 64.0f
#define IMG_PX  448.0f

// grid-wide accumulator (zero-initialized at module load; reset by the last
// finishing block -> deterministic across graph replays, no zeroing kernel)
__device__ float        g_acc;
__device__ unsigned int g_done;

__device__ __forceinline__ uint32_t smem_u32(const void* p) {
    uint32_t a;
    asm("{ .reg .u64 t; cvta.to.shared.u64 t, %1; cvt.u32.u64 %0, t; }"
        : "=r"(a) : "l"(p));
    return a;
}

__device__ __forceinline__ float4 decode_box(float p0, float p1, float p2, float p3,
                                             float gx, float gy) {
    float cx = p0 * CELL_PX + gx;
    float cy = p1 * CELL_PX + gy;
    float w  = p2 * IMG_PX;
    float h  = p3 * IMG_PX;
    float4 r;
    r.x = fminf(fmaxf(cx - w * 0.5f, 0.0f), IMG_PX);
    r.y = fminf(fmaxf(cy - h * 0.5f, 0.0f), IMG_PX);
    r.z = fminf(fmaxf(cx + w * 0.5f, 0.0f), IMG_PX);
    r.w = fminf(fmaxf(cy + h * 0.5f, 0.0f), IMG_PX);
    return r;
}

__device__ __forceinline__ float iou_fn(float4 a, float4 b) {
    float l  = fmaxf(a.x, b.x);
    float r  = fminf(a.z, b.z);
    float tt = fmaxf(a.y, b.y);
    float bo = fminf(a.w, b.w);
    bool m = (l < r) && (tt < bo);
    float inter = (r - l) * (bo - tt);
    float uni = (a.z - a.x) * (a.w - a.y) + (b.z - b.x) * (b.w - b.y);
    return m ? inter / (uni - inter) : 0.0f;
}

__global__ __launch_bounds__(BLOCK) void yolo_loss_kernel(
    const float* __restrict__ inp,   // [B, 30, 7, 7]
    const float* __restrict__ tgt,   // [B, 7, 7, 30]  == [N_CELLS, 30]
    float* __restrict__ out)
{
    __shared__ alignas(16) float st[BLOCK * CH];   // contiguous target slab, 30720 B
    __shared__ alignas(8)  uint64_t mbar;
    __shared__ float warp_sums[BLOCK / 32];

    const int tid = threadIdx.x;
    const int n0  = blockIdx.x * BLOCK;
    const uint32_t mbar_a = smem_u32(&mbar);

    if (tid == 0)
        asm volatile("mbarrier.init.shared.b64 [%0], 1;" :: "r"(mbar_a) : "memory");
    __syncthreads();

    // ---- single bulk copy for the whole target slab (no per-thread LSU cost) ----
    if (tid == 0) {
        asm volatile("mbarrier.arrive.expect_tx.shared.b64 _, [%0], %1;"
                     :: "r"(mbar_a), "r"((uint32_t)SLAB_BYTES) : "memory");
        const char* src = reinterpret_cast<const char*>(tgt) + (size_t)n0 * (CH * 4);
        asm volatile("cp.async.bulk.shared::cluster.global.mbarrier::complete_tx::bytes "
                     "[%0], [%1], %2, [%3];"
                     :: "r"(smem_u32(st)), "l"(src), "r"((uint32_t)SLAB_BYTES), "r"(mbar_a)
                     : "memory");
    }

    // ---- issue all 30 input loads while the bulk copy streams ----
    const int n    = n0 + tid;
    const int b    = n / CELLS_PER_B;
    const int cell = n - b * CELLS_PER_B;
    const int row  = cell / S_GRID;
    const int col  = cell - row * S_GRID;
    const float gx = (float)col * CELL_PX;
    const float gy = (float)row * CELL_PX;

    // input: channel-major, stride 49 per channel; contiguous across threads
    const float* xb = inp + (size_t)b * (CH * CELLS_PER_B) + cell;
    float x[CH];
    #pragma unroll
    for (int c = 0; c < CH; c++)
        x[c] = __ldg(&xb[c * CELLS_PER_B]);

    // ---- wait for the slab (phase 0; barrier freshly initialized each launch) ----
    {
        uint32_t done;
        asm volatile(
            "{\n\t.reg .pred p;\n\t"
            "mbarrier.try_wait.parity.acquire.cta.shared::cta.b64 p, [%1], 0;\n\t"
            "selp.b32 %0, 1, 0, p;\n\t}"
            : "=r"(done) : "r"(mbar_a) : "memory");
        if (!done) {
            asm volatile(
                "{\n\t.reg .pred P1;\n\t"
                "WL_%=:\n\t"
                "mbarrier.try_wait.parity.acquire.cta.shared::cta.b64 P1, [%0], 0, 0x989680;\n\t"
                "@P1 bra.uni WD_%=;\n\t"
                "bra.uni WL_%=;\n\t"
                "WD_%=:\n\t}"
                :: "r"(mbar_a) : "memory");
        }
    }
    __syncthreads();

    const float* t = st + tid * CH;

    float4 pb1 = decode_box(x[0], x[1], x[2], x[3], gx, gy);
    float4 pb2 = decode_box(x[5], x[6], x[7], x[8], gx, gy);
    float4 tb1 = decode_box(t[0], t[1], t[2], t[3], gx, gy);
    float4 tb2 = decode_box(t[5], t[6], t[7], t[8], gx, gy);

    float iou1 = iou_fn(pb1, tb1);
    float iou2 = iou_fn(pb2, tb2);
    bool  mask = iou1 < iou2;
    float iou  = mask ? iou2 : iou1;

    float s0 = mask ? x[5] : x[0];
    float s1 = mask ? x[6] : x[1];
    float s2 = mask ? x[7] : x[2];
    float s3 = mask ? x[8] : x[3];
    float s4 = mask ? x[9] : x[4];

    float w = (t[4] == 1.0f) ? 1.0f : 0.0f;

    float d0 = s0 - t[0], d1 = s1 - t[1];
    float coord = d0 * d0 + d1 * d1;
    float e2 = sqrtf(s2) - sqrtf(t[2]);
    float e3 = sqrtf(s3) - sqrtf(t[3]);
    float size = e2 * e2 + e3 * e3;
    float dc = s4 - iou;
    float conf = dc * dc;
    float noobj = s4 * s4;

    float cls = 0.0f;
    #pragma unroll
    for (int c = 10; c < CH; c++) {
        float d = x[c] - t[c];
        cls += d * d;
    }

    float loss = w * (5.0f * coord + 5.0f * size + conf + cls)
               + (1.0f - w) * 0.5f * noobj;

    // ---- block reduction ----
    #pragma unroll
    for (int o = 16; o > 0; o >>= 1)
        loss += __shfl_down_sync(0xFFFFFFFFu, loss, o);

    const int lane = tid & 31;
    const int wid  = tid >> 5;
    if (lane == 0) warp_sums[wid] = loss;
    __syncthreads();

    if (tid == 0) {
        float v = 0.0f;
        #pragma unroll
        for (int i = 0; i < BLOCK / 32; i++) v += warp_sums[i];

        atomicAdd(&g_acc, v);
        __threadfence();
        unsigned int done = atomicAdd(&g_done, 1u);
        if (done == GRID_N - 1) {
            out[0] = g_acc;      // publish result
            g_acc  = 0.0f;       // reset for next graph replay
            g_done = 0u;
        }
    }
}

extern "C" void kernel_launch(void* const* d_in, const int* in_sizes, int n_in,
                              void* d_out, int out_size) {
    const float* inp = (const float*)d_in[0];   // [16384, 30, 7, 7]
    const float* tgt = (const float*)d_in[1];   // [16384, 7, 7, 30]
    float* out = (float*)d_out;                 // scalar

    yolo_loss_kernel<<<GRID_N, BLOCK>>>(inp, tgt, out);
}